// round 15
// baseline (speedup 1.0000x reference)
#include <cuda_runtime.h>
#include <cuda_fp16.h>

#define NN 100000
#define NE 3200000
#define DF 128
#define H1 32
#define H2 16
#define NC 8
#define NBLK 391          // ceil(NN/256)
#define GT 128            // gemm1 node tile per block

// ---- scratch (device globals; zero-initialized at load; no allocs) ----
__device__ __align__(16) __half2 g_g1h[NN * (H1 / 2)]; // g1 fp16 (row = 64 B)
__device__ __align__(16) __half2 g_g2h[NN * (H2 / 2)]; // g2 fp16 (row = 32 B)
__device__ float g_dinv[NN];
__device__ int   g_cnt[NN];      // zero at entry; re-zeroed by k_scan_block
__device__ int   g_off[NN + 1];
__device__ int   g_cur[NN];
__device__ int   g_bsum[NBLK + 1];
__device__ int   g_bpref[NBLK + 1];
__device__ int   g_csr[NE];

// ---- K1: degree histogram, int4-vectorized (4 edges/thread) ----
__global__ void k_deg(const int* __restrict__ ei) {
    int i = blockIdx.x * blockDim.x + threadIdx.x;
    int4 d = __ldg((const int4*)(ei + NE) + i);
    atomicAdd(&g_cnt[d.x], 1);
    atomicAdd(&g_cnt[d.y], 1);
    atomicAdd(&g_cnt[d.z], 1);
    atomicAdd(&g_cnt[d.w], 1);
}

// ---- K2: per-block exclusive scan of cnt (+ dinv, + cnt re-zero) ----
__global__ void k_scan_block() {
    __shared__ int swarp[8];
    __shared__ int soff[8];
    int t = threadIdx.x;
    int i = blockIdx.x * 256 + t;
    int v = 0;
    if (i < NN) {
        v = g_cnt[i];
        g_cnt[i] = 0;
        g_dinv[i] = rsqrtf((float)(v + 1));
    }
    int incl = v;
#pragma unroll
    for (int d = 1; d < 32; d <<= 1) {
        int n = __shfl_up_sync(~0u, incl, d);
        if ((t & 31) >= d) incl += n;
    }
    if ((t & 31) == 31) swarp[t >> 5] = incl;
    __syncthreads();
    if (t == 0) {
        int run = 0;
#pragma unroll
        for (int w = 0; w < 8; w++) { soff[w] = run; run += swarp[w]; }
        g_bsum[blockIdx.x] = run;
    }
    __syncthreads();
    if (i < NN) g_off[i] = incl - v + soff[t >> 5];
}

// ---- K3: scan 391 block sums with ONE WARP ----
__global__ void k_scan_top() {
    const int PER = (NBLK + 31) / 32;   // 13
    int lane = threadIdx.x;
    int base = lane * PER;
    int pre[PER];
    int s = 0;
#pragma unroll
    for (int i = 0; i < PER; i++) {
        int idx = base + i;
        int v = (idx < NBLK) ? g_bsum[idx] : 0;
        pre[i] = s;
        s += v;
    }
    int incl = s;
#pragma unroll
    for (int d = 1; d < 32; d <<= 1) {
        int n = __shfl_up_sync(~0u, incl, d);
        if (lane >= d) incl += n;
    }
    int excl = incl - s;
#pragma unroll
    for (int i = 0; i < PER; i++) {
        int idx = base + i;
        if (idx < NBLK) g_bpref[idx] = excl + pre[i];
    }
}

// ---- K4 (slot 4, profiled): g1 = (x @ W1) * dinv -> fp16 packed ----
// Register-tiled: 256 threads, block tile 128n x 32j, thread tile 4n x 4j.
// x staged k-major (transposed) in smem: per k, x read = conflict-free LDS.128,
// W read = warp-broadcast LDS.128  ->  2 B crossbar per lane-FMA.
__global__ void k_gemm1(const float* __restrict__ x, const float* __restrict__ W1) {
    __shared__ float sW[DF * H1];          // [k][j] row-major, 16 KB
    __shared__ float sxT[64][GT + 4];      // k-chunk transposed, 33 KB
    int tid = threadIdx.x;
    int tn = tid & 31;                     // node group (4 nodes each)
    int tj = tid >> 5;                     // col group (4 cols each)
    int node0 = blockIdx.x * GT;
    int valid = NN - node0; if (valid > GT) valid = GT;

    for (int i = tid; i < DF * H1; i += 256) sW[i] = W1[i];

    float acc[4][4] = {};
    int r  = tid >> 1;                     // node row this thread stages
    int kh = (tid & 1) * 32;               // k half within chunk

#pragma unroll
    for (int kc = 0; kc < DF; kc += 64) {
        __syncthreads();                   // first iter: also covers sW fill
        if (r < valid) {
            const float4* src = (const float4*)(x + (size_t)(node0 + r) * DF + kc + kh);
#pragma unroll
            for (int i = 0; i < 8; i++) {
                float4 v = src[i];
                int k = kh + i * 4;
                sxT[k + 0][r] = v.x; sxT[k + 1][r] = v.y;
                sxT[k + 2][r] = v.z; sxT[k + 3][r] = v.w;
            }
        }
        __syncthreads();
#pragma unroll
        for (int k = 0; k < 64; k++) {
            float4 xv = *(const float4*)&sxT[k][tn * 4];
            float4 wv = *(const float4*)&sW[(kc + k) * H1 + tj * 4];
            acc[0][0] += xv.x * wv.x; acc[0][1] += xv.x * wv.y;
            acc[0][2] += xv.x * wv.z; acc[0][3] += xv.x * wv.w;
            acc[1][0] += xv.y * wv.x; acc[1][1] += xv.y * wv.y;
            acc[1][2] += xv.y * wv.z; acc[1][3] += xv.y * wv.w;
            acc[2][0] += xv.z * wv.x; acc[2][1] += xv.z * wv.y;
            acc[2][2] += xv.z * wv.z; acc[2][3] += xv.z * wv.w;
            acc[3][0] += xv.w * wv.x; acc[3][1] += xv.w * wv.y;
            acc[3][2] += xv.w * wv.z; acc[3][3] += xv.w * wv.w;
        }
    }
    // epilogue: scale by dinv, pack 4 cols -> 2 half2 (uint2 store) per node
#pragma unroll
    for (int i = 0; i < 4; i++) {
        int nl = tn * 4 + i;
        if (nl < valid) {
            int n = node0 + nl;
            float dv = g_dinv[n];
            __half2 h0 = __floats2half2_rn(acc[i][0] * dv, acc[i][1] * dv);
            __half2 h1 = __floats2half2_rn(acc[i][2] * dv, acc[i][3] * dv);
            uint2 pk = make_uint2(*(unsigned*)&h0, *(unsigned*)&h1);
            *((uint2*)&g_g1h[(size_t)n * (H1 / 2) + tj * 2]) = pk;
        }
    }
}

// ---- K5: add block prefixes; init cursors; off[NN]=NE ----
__global__ void k_scan_add() {
    int i = blockIdx.x * blockDim.x + threadIdx.x;
    if (i < NN) {
        int o = g_off[i] + g_bpref[i >> 8];
        g_off[i] = o;
        g_cur[i] = o;
    }
    if (i == 0) g_off[NN] = NE;
}

// ---- K6: place edges into CSR slots, int4-vectorized ----
__global__ void k_place(const int* __restrict__ ei) {
    int i = blockIdx.x * blockDim.x + threadIdx.x;
    int4 s = __ldg((const int4*)ei + i);
    int4 d = __ldg((const int4*)(ei + NE) + i);
    int p;
    p = atomicAdd(&g_cur[d.x], 1); g_csr[p] = s.x;
    p = atomicAdd(&g_cur[d.y], 1); g_csr[p] = s.y;
    p = atomicAdd(&g_cur[d.z], 1); g_csr[p] = s.z;
    p = atomicAdd(&g_cur[d.w], 1); g_csr[p] = s.w;
}

__device__ __forceinline__ void acc8(float* a, uint4 v) {
    float2 f0 = __half22float2(*(__half2*)&v.x);
    float2 f1 = __half22float2(*(__half2*)&v.y);
    float2 f2 = __half22float2(*(__half2*)&v.z);
    float2 f3 = __half22float2(*(__half2*)&v.w);
    a[0] += f0.x; a[1] += f0.y; a[2] += f1.x; a[3] += f1.y;
    a[4] += f2.x; a[5] += f2.y; a[6] += f3.x; a[7] += f3.y;
}

// ---- K7: gather layer-1 + relu + W2 matvec -> g2 fp16 ----
__global__ void k_gather_mid(const float* __restrict__ b1, const float* __restrict__ W2) {
    __shared__ float sW2[H1 * H2];
    __shared__ float su[8][H1 + 4];
    int tid = threadIdx.x;
    for (int i = tid; i < H1 * H2; i += 256) sW2[i] = W2[i];
    __syncthreads();
    int warp = tid >> 5, lane = tid & 31;
    int node = blockIdx.x * 8 + warp;
    int slot = lane >> 2, q = lane & 3;
    int s = g_off[node], t = g_off[node + 1];
    float a[8] = {0.f, 0.f, 0.f, 0.f, 0.f, 0.f, 0.f, 0.f};
    int e = s + slot;
    for (; e + 8 < t; e += 16) {
        int s0 = __ldg(&g_csr[e]);
        int s1 = __ldg(&g_csr[e + 8]);
        uint4 v0 = __ldg((const uint4*)(g_g1h + s0 * (H1 / 2)) + q);
        uint4 v1 = __ldg((const uint4*)(g_g1h + s1 * (H1 / 2)) + q);
        acc8(a, v0);
        acc8(a, v1);
    }
    if (e < t) {
        int s0 = __ldg(&g_csr[e]);
        uint4 v0 = __ldg((const uint4*)(g_g1h + s0 * (H1 / 2)) + q);
        acc8(a, v0);
    }
#pragma unroll
    for (int m = 4; m < 32; m <<= 1)
#pragma unroll
        for (int i = 0; i < 8; i++)
            a[i] += __shfl_xor_sync(~0u, a[i], m);
    uint4 sv = *((const uint4*)(g_g1h + node * (H1 / 2)) + q);
    float sl[8] = {0.f, 0.f, 0.f, 0.f, 0.f, 0.f, 0.f, 0.f};
    acc8(sl, sv);
    float dinv = g_dinv[node];
    if (slot == 0) {
        float u[8];
#pragma unroll
        for (int i = 0; i < 8; i++)
            u[i] = fmaxf(fmaf(a[i] + sl[i], dinv, __ldg(&b1[8 * q + i])), 0.f);
        ((float4*)&su[warp][8 * q])[0] = make_float4(u[0], u[1], u[2], u[3]);
        ((float4*)&su[warp][8 * q])[1] = make_float4(u[4], u[5], u[6], u[7]);
    }
    __syncwarp();
    int col = lane & 15;
    float acc = 0.f;
#pragma unroll
    for (int k = 0; k < H1; k++)
        acc = fmaf(su[warp][k], sW2[k * H2 + col], acc);
    acc *= dinv;
    float nb = __shfl_down_sync(~0u, acc, 1);
    if (lane < 16 && (lane & 1) == 0)
        g_g2h[node * (H2 / 2) + (lane >> 1)] = __floats2half2_rn(acc, nb);
}

__device__ __forceinline__ void acc4(float* a, uint2 v) {
    float2 f0 = __half22float2(*(__half2*)&v.x);
    float2 f1 = __half22float2(*(__half2*)&v.y);
    a[0] += f0.x; a[1] += f0.y; a[2] += f1.x; a[3] += f1.y;
}

// ---- K8: gather layer-2 + relu + Wc + log_softmax -> out (FUSED) ----
__global__ void k_gather2_final(const float* __restrict__ b2,
                                const float* __restrict__ Wc,
                                const float* __restrict__ bc,
                                float* __restrict__ out) {
    __shared__ float su[8][H2 + 4];   // 80 B rows, 16B-aligned
    int tid = threadIdx.x;
    int warp = tid >> 5, lane = tid & 31;
    int node = blockIdx.x * 8 + warp;
    int slot = lane >> 2, q = lane & 3;
    int s = g_off[node], t = g_off[node + 1];
    float a[4] = {0.f, 0.f, 0.f, 0.f};
    int e = s + slot;
    for (; e + 8 < t; e += 16) {
        int s0 = __ldg(&g_csr[e]);
        int s1 = __ldg(&g_csr[e + 8]);
        uint2 v0 = __ldg((const uint2*)(g_g2h + s0 * (H2 / 2)) + q);
        uint2 v1 = __ldg((const uint2*)(g_g2h + s1 * (H2 / 2)) + q);
        acc4(a, v0);
        acc4(a, v1);
    }
    if (e < t) {
        int s0 = __ldg(&g_csr[e]);
        uint2 v0 = __ldg((const uint2*)(g_g2h + s0 * (H2 / 2)) + q);
        acc4(a, v0);
    }
#pragma unroll
    for (int m = 4; m < 32; m <<= 1)
#pragma unroll
        for (int i = 0; i < 4; i++)
            a[i] += __shfl_xor_sync(~0u, a[i], m);
    float dinv = g_dinv[node];
    if (slot == 0) {
        uint2 sv = *((const uint2*)(g_g2h + node * (H2 / 2)) + q);
        acc4(a, sv);   // self loop
        float u0 = fmaxf(fmaf(a[0], dinv, __ldg(&b2[4 * q + 0])), 0.f);
        float u1 = fmaxf(fmaf(a[1], dinv, __ldg(&b2[4 * q + 1])), 0.f);
        float u2 = fmaxf(fmaf(a[2], dinv, __ldg(&b2[4 * q + 2])), 0.f);
        float u3 = fmaxf(fmaf(a[3], dinv, __ldg(&b2[4 * q + 3])), 0.f);
        *((float4*)&su[warp][4 * q]) = make_float4(u0, u1, u2, u3);
    }
    __syncwarp();
    int j = lane & 7;
    float l = __ldg(&bc[j]);
#pragma unroll
    for (int k = 0; k < H2; k++)
        l = fmaf(su[warp][k], __ldg(&Wc[k * NC + j]), l);
    float m = l;
#pragma unroll
    for (int d = 1; d < 8; d <<= 1)
        m = fmaxf(m, __shfl_xor_sync(~0u, m, d, 8));
    float ex = expf(l - m);
    float sum = ex;
#pragma unroll
    for (int d = 1; d < 8; d <<= 1)
        sum += __shfl_xor_sync(~0u, sum, d, 8);
    float lse = m + logf(sum);
    if (lane < 8)
        out[(size_t)node * NC + j] = l - lse;
}

extern "C" void kernel_launch(void* const* d_in, const int* in_sizes, int n_in,
                              void* d_out, int out_size) {
    (void)out_size;
    const float* x  = nullptr; const int* ei = nullptr;
    const float* W1 = nullptr; const float* b1 = nullptr;
    const float* W2 = nullptr; const float* b2 = nullptr;
    const float* Wc = nullptr; const float* bc = nullptr;
    for (int i = 0; i < n_in; i++) {
        switch (in_sizes[i]) {
            case NN * DF:    x  = (const float*)d_in[i]; break;
            case 2 * NE:     ei = (const int*)d_in[i];   break;
            case DF * H1:    W1 = (const float*)d_in[i]; break;
            case H1 * H2:    W2 = (const float*)d_in[i]; break;
            case H2 * NC:    Wc = (const float*)d_in[i]; break;
            case H1:         b1 = (const float*)d_in[i]; break;
            case H2:         b2 = (const float*)d_in[i]; break;
            case NC:         bc = (const float*)d_in[i]; break;
            default: break;
        }
    }
    float* out = (float*)d_out;

    k_deg<<<NE / 4 / 256, 256>>>(ei);                    // 1
    k_scan_block<<<NBLK, 256>>>();                       // 2
    k_scan_top<<<1, 32>>>();                             // 3
    k_gemm1<<<(NN + GT - 1) / GT, 256>>>(x, W1);         // 4  <- profiled slot
    k_scan_add<<<NBLK, 256>>>();                         // 5
    k_place<<<NE / 4 / 256, 256>>>(ei);                  // 6
    k_gather_mid<<<NN / 8, 256>>>(b1, W2);               // 7
    k_gather2_final<<<NN / 8, 256>>>(b2, Wc, bc, out);   // 8
}

// round 16
// speedup vs baseline: 1.0265x; 1.0265x over previous
#include <cuda_runtime.h>
#include <cuda_fp16.h>
#include <cstdint>

#define NN 100000
#define NE 3200000
#define DF 128
#define H1 32
#define H2 16
#define NC 8
#define NBLK 391          // ceil(NN/256)
#define GT 128            // gemm1 node tile per block
#define XPAD 136          // padded row length (halfs): 272 B, 16B-aligned, LDSM conflict-free

// ---- scratch (device globals; zero-initialized at load; no allocs) ----
__device__ __align__(16) __half2 g_g1h[NN * (H1 / 2)]; // g1 fp16 (row = 64 B)
__device__ __align__(16) __half2 g_g2h[NN * (H2 / 2)]; // g2 fp16 (row = 32 B)
__device__ float g_dinv[NN];
__device__ int   g_cnt[NN];      // zero at entry; re-zeroed by k_scan_block
__device__ int   g_off[NN + 1];
__device__ int   g_cur[NN];
__device__ int   g_bsum[NBLK + 1];
__device__ int   g_bpref[NBLK + 1];
__device__ int   g_csr[NE];

// ---- K1: degree histogram, int4-vectorized (4 edges/thread) ----
__global__ void k_deg(const int* __restrict__ ei) {
    int i = blockIdx.x * blockDim.x + threadIdx.x;
    int4 d = __ldg((const int4*)(ei + NE) + i);
    atomicAdd(&g_cnt[d.x], 1);
    atomicAdd(&g_cnt[d.y], 1);
    atomicAdd(&g_cnt[d.z], 1);
    atomicAdd(&g_cnt[d.w], 1);
}

// ---- K2: per-block exclusive scan of cnt (+ dinv, + cnt re-zero) ----
__global__ void k_scan_block() {
    __shared__ int swarp[8];
    __shared__ int soff[8];
    int t = threadIdx.x;
    int i = blockIdx.x * 256 + t;
    int v = 0;
    if (i < NN) {
        v = g_cnt[i];
        g_cnt[i] = 0;
        g_dinv[i] = rsqrtf((float)(v + 1));
    }
    int incl = v;
#pragma unroll
    for (int d = 1; d < 32; d <<= 1) {
        int n = __shfl_up_sync(~0u, incl, d);
        if ((t & 31) >= d) incl += n;
    }
    if ((t & 31) == 31) swarp[t >> 5] = incl;
    __syncthreads();
    if (t == 0) {
        int run = 0;
#pragma unroll
        for (int w = 0; w < 8; w++) { soff[w] = run; run += swarp[w]; }
        g_bsum[blockIdx.x] = run;
    }
    __syncthreads();
    if (i < NN) g_off[i] = incl - v + soff[t >> 5];
}

// ---- K3: scan 391 block sums with ONE WARP ----
__global__ void k_scan_top() {
    const int PER = (NBLK + 31) / 32;   // 13
    int lane = threadIdx.x;
    int base = lane * PER;
    int pre[PER];
    int s = 0;
#pragma unroll
    for (int i = 0; i < PER; i++) {
        int idx = base + i;
        int v = (idx < NBLK) ? g_bsum[idx] : 0;
        pre[i] = s;
        s += v;
    }
    int incl = s;
#pragma unroll
    for (int d = 1; d < 32; d <<= 1) {
        int n = __shfl_up_sync(~0u, incl, d);
        if (lane >= d) incl += n;
    }
    int excl = incl - s;
#pragma unroll
    for (int i = 0; i < PER; i++) {
        int idx = base + i;
        if (idx < NBLK) g_bpref[idx] = excl + pre[i];
    }
}

// ---- HMMA helpers ----
__device__ __forceinline__ void ldmatrix_x4(uint32_t& d0, uint32_t& d1,
                                            uint32_t& d2, uint32_t& d3,
                                            uint32_t addr) {
    asm volatile("ldmatrix.sync.aligned.m8n8.x4.shared.b16 {%0,%1,%2,%3}, [%4];"
                 : "=r"(d0), "=r"(d1), "=r"(d2), "=r"(d3) : "r"(addr));
}
__device__ __forceinline__ void mma16816(float* c, uint32_t a0, uint32_t a1,
                                         uint32_t a2, uint32_t a3,
                                         uint32_t b0, uint32_t b1) {
    asm volatile(
        "mma.sync.aligned.m16n8k16.row.col.f32.f16.f16.f32 "
        "{%0,%1,%2,%3}, {%4,%5,%6,%7}, {%8,%9}, {%0,%1,%2,%3};"
        : "+f"(c[0]), "+f"(c[1]), "+f"(c[2]), "+f"(c[3])
        : "r"(a0), "r"(a1), "r"(a2), "r"(a3), "r"(b0), "r"(b1));
}

// ---- K4 (slot 4, profiled): g1 = (x @ W1) * dinv via HMMA -> fp16 packed ----
// 256 thr = 8 warps; block tile 128 nodes x 32 cols; warp tile 16 nodes x 32 cols.
// x staged fp16 [128][XPAD] (272 B rows), W1^T staged fp16 [32][XPAD].
__global__ void k_gemm1(const float* __restrict__ x, const float* __restrict__ W1) {
    __shared__ __half sxh[GT][XPAD];    // 34.8 KB
    __shared__ __half sWt[H1][XPAD];    //  8.7 KB
    int tid = threadIdx.x;
    int node0 = blockIdx.x * GT;
    int valid = NN - node0; if (valid > GT) valid = GT;

    // stage W1^T: sWt[j][k] = W1[k][j]
    for (int i = tid; i < DF * H1; i += 256) {
        int k = i >> 5, j = i & 31;
        sWt[j][k] = __float2half(W1[i]);
    }
    // stage x as fp16: thread -> row tid>>1, 64-feat segment (tid&1)
    {
        int r = tid >> 1, seg = (tid & 1) * 64;
        if (r < valid) {
            const float4* src = (const float4*)(x + (size_t)(node0 + r) * DF + seg);
#pragma unroll
            for (int i = 0; i < 16; i++) {
                float4 v = src[i];
                __half2 h0 = __floats2half2_rn(v.x, v.y);
                __half2 h1 = __floats2half2_rn(v.z, v.w);
                *(uint2*)&sxh[r][seg + i * 4] =
                    make_uint2(*(unsigned*)&h0, *(unsigned*)&h1);
            }
        } else {
#pragma unroll
            for (int i = 0; i < 16; i++)
                *(uint2*)&sxh[r][seg + i * 4] = make_uint2(0u, 0u);
        }
    }
    __syncthreads();

    int warp = tid >> 5, lane = tid & 31;
    float c[4][4] = {};                 // 4 n-tiles x 4 floats
    // A-fragment lane address: row = warp*16 + (lane&15), col-halfs = (lane>>4)*8
    uint32_t a_base = (uint32_t)__cvta_generic_to_shared(
        &sxh[warp * 16 + (lane & 15)][(lane >> 4) * 8]);
    int bn = lane >> 2;                 // B fragment: n within tile
    int bk = (lane & 3) * 2;            // B fragment: k pair base

#pragma unroll
    for (int kc = 0; kc < DF; kc += 16) {
        uint32_t a0, a1, a2, a3;
        ldmatrix_x4(a0, a1, a2, a3, a_base + kc * 2);
#pragma unroll
        for (int t = 0; t < 4; t++) {
            uint32_t b0 = *(const uint32_t*)&sWt[t * 8 + bn][kc + bk];
            uint32_t b1 = *(const uint32_t*)&sWt[t * 8 + bn][kc + bk + 8];
            mma16816(c[t], a0, a1, a2, a3, b0, b1);
        }
    }

    // epilogue: rows r0 and r0+8; cols pair = t*8 + (lane&3)*2 -> half2 idx t*4+(lane&3)
    int r0 = warp * 16 + (lane >> 2);
    int na = node0 + r0, nb = na + 8;
    float dva = (r0 < valid)     ? g_dinv[na] : 0.f;
    float dvb = (r0 + 8 < valid) ? g_dinv[nb] : 0.f;
#pragma unroll
    for (int t = 0; t < 4; t++) {
        int hidx = t * 4 + (lane & 3);
        if (r0 < valid)
            g_g1h[(size_t)na * (H1 / 2) + hidx] =
                __floats2half2_rn(c[t][0] * dva, c[t][1] * dva);
        if (r0 + 8 < valid)
            g_g1h[(size_t)nb * (H1 / 2) + hidx] =
                __floats2half2_rn(c[t][2] * dvb, c[t][3] * dvb);
    }
}

// ---- K5: add block prefixes; init cursors; off[NN]=NE ----
__global__ void k_scan_add() {
    int i = blockIdx.x * blockDim.x + threadIdx.x;
    if (i < NN) {
        int o = g_off[i] + g_bpref[i >> 8];
        g_off[i] = o;
        g_cur[i] = o;
    }
    if (i == 0) g_off[NN] = NE;
}

// ---- K6: place edges into CSR slots, int4-vectorized ----
__global__ void k_place(const int* __restrict__ ei) {
    int i = blockIdx.x * blockDim.x + threadIdx.x;
    int4 s = __ldg((const int4*)ei + i);
    int4 d = __ldg((const int4*)(ei + NE) + i);
    int p;
    p = atomicAdd(&g_cur[d.x], 1); g_csr[p] = s.x;
    p = atomicAdd(&g_cur[d.y], 1); g_csr[p] = s.y;
    p = atomicAdd(&g_cur[d.z], 1); g_csr[p] = s.z;
    p = atomicAdd(&g_cur[d.w], 1); g_csr[p] = s.w;
}

__device__ __forceinline__ void acc8(float* a, uint4 v) {
    float2 f0 = __half22float2(*(__half2*)&v.x);
    float2 f1 = __half22float2(*(__half2*)&v.y);
    float2 f2 = __half22float2(*(__half2*)&v.z);
    float2 f3 = __half22float2(*(__half2*)&v.w);
    a[0] += f0.x; a[1] += f0.y; a[2] += f1.x; a[3] += f1.y;
    a[4] += f2.x; a[5] += f2.y; a[6] += f3.x; a[7] += f3.y;
}

// ---- K7: gather layer-1 + relu + W2 matvec -> g2 fp16 ----
__global__ void k_gather_mid(const float* __restrict__ b1, const float* __restrict__ W2) {
    __shared__ float sW2[H1 * H2];
    __shared__ float su[8][H1 + 4];
    int tid = threadIdx.x;
    for (int i = tid; i < H1 * H2; i += 256) sW2[i] = W2[i];
    __syncthreads();
    int warp = tid >> 5, lane = tid & 31;
    int node = blockIdx.x * 8 + warp;
    int slot = lane >> 2, q = lane & 3;
    int s = g_off[node], t = g_off[node + 1];
    float a[8] = {0.f, 0.f, 0.f, 0.f, 0.f, 0.f, 0.f, 0.f};
    int e = s + slot;
    for (; e + 8 < t; e += 16) {
        int s0 = __ldg(&g_csr[e]);
        int s1 = __ldg(&g_csr[e + 8]);
        uint4 v0 = __ldg((const uint4*)(g_g1h + s0 * (H1 / 2)) + q);
        uint4 v1 = __ldg((const uint4*)(g_g1h + s1 * (H1 / 2)) + q);
        acc8(a, v0);
        acc8(a, v1);
    }
    if (e < t) {
        int s0 = __ldg(&g_csr[e]);
        uint4 v0 = __ldg((const uint4*)(g_g1h + s0 * (H1 / 2)) + q);
        acc8(a, v0);
    }
#pragma unroll
    for (int m = 4; m < 32; m <<= 1)
#pragma unroll
        for (int i = 0; i < 8; i++)
            a[i] += __shfl_xor_sync(~0u, a[i], m);
    uint4 sv = *((const uint4*)(g_g1h + node * (H1 / 2)) + q);
    float sl[8] = {0.f, 0.f, 0.f, 0.f, 0.f, 0.f, 0.f, 0.f};
    acc8(sl, sv);
    float dinv = g_dinv[node];
    if (slot == 0) {
        float u[8];
#pragma unroll
        for (int i = 0; i < 8; i++)
            u[i] = fmaxf(fmaf(a[i] + sl[i], dinv, __ldg(&b1[8 * q + i])), 0.f);
        ((float4*)&su[warp][8 * q])[0] = make_float4(u[0], u[1], u[2], u[3]);
        ((float4*)&su[warp][8 * q])[1] = make_float4(u[4], u[5], u[6], u[7]);
    }
    __syncwarp();
    int col = lane & 15;
    float acc = 0.f;
#pragma unroll
    for (int k = 0; k < H1; k++)
        acc = fmaf(su[warp][k], sW2[k * H2 + col], acc);
    acc *= dinv;
    float nb = __shfl_down_sync(~0u, acc, 1);
    if (lane < 16 && (lane & 1) == 0)
        g_g2h[node * (H2 / 2) + (lane >> 1)] = __floats2half2_rn(acc, nb);
}

__device__ __forceinline__ void acc4(float* a, uint2 v) {
    float2 f0 = __half22float2(*(__half2*)&v.x);
    float2 f1 = __half22float2(*(__half2*)&v.y);
    a[0] += f0.x; a[1] += f0.y; a[2] += f1.x; a[3] += f1.y;
}

// ---- K8: gather layer-2 + relu + Wc + log_softmax -> out (FUSED) ----
__global__ void k_gather2_final(const float* __restrict__ b2,
                                const float* __restrict__ Wc,
                                const float* __restrict__ bc,
                                float* __restrict__ out) {
    __shared__ float su[8][H2 + 4];   // 80 B rows, 16B-aligned
    int tid = threadIdx.x;
    int warp = tid >> 5, lane = tid & 31;
    int node = blockIdx.x * 8 + warp;
    int slot = lane >> 2, q = lane & 3;
    int s = g_off[node], t = g_off[node + 1];
    float a[4] = {0.f, 0.f, 0.f, 0.f};
    int e = s + slot;
    for (; e + 8 < t; e += 16) {
        int s0 = __ldg(&g_csr[e]);
        int s1 = __ldg(&g_csr[e + 8]);
        uint2 v0 = __ldg((const uint2*)(g_g2h + s0 * (H2 / 2)) + q);
        uint2 v1 = __ldg((const uint2*)(g_g2h + s1 * (H2 / 2)) + q);
        acc4(a, v0);
        acc4(a, v1);
    }
    if (e < t) {
        int s0 = __ldg(&g_csr[e]);
        uint2 v0 = __ldg((const uint2*)(g_g2h + s0 * (H2 / 2)) + q);
        acc4(a, v0);
    }
#pragma unroll
    for (int m = 4; m < 32; m <<= 1)
#pragma unroll
        for (int i = 0; i < 4; i++)
            a[i] += __shfl_xor_sync(~0u, a[i], m);
    float dinv = g_dinv[node];
    if (slot == 0) {
        uint2 sv = *((const uint2*)(g_g2h + node * (H2 / 2)) + q);
        acc4(a, sv);   // self loop
        float u0 = fmaxf(fmaf(a[0], dinv, __ldg(&b2[4 * q + 0])), 0.f);
        float u1 = fmaxf(fmaf(a[1], dinv, __ldg(&b2[4 * q + 1])), 0.f);
        float u2 = fmaxf(fmaf(a[2], dinv, __ldg(&b2[4 * q + 2])), 0.f);
        float u3 = fmaxf(fmaf(a[3], dinv, __ldg(&b2[4 * q + 3])), 0.f);
        *((float4*)&su[warp][4 * q]) = make_float4(u0, u1, u2, u3);
    }
    __syncwarp();
    int j = lane & 7;
    float l = __ldg(&bc[j]);
#pragma unroll
    for (int k = 0; k < H2; k++)
        l = fmaf(su[warp][k], __ldg(&Wc[k * NC + j]), l);
    float m = l;
#pragma unroll
    for (int d = 1; d < 8; d <<= 1)
        m = fmaxf(m, __shfl_xor_sync(~0u, m, d, 8));
    float ex = expf(l - m);
    float sum = ex;
#pragma unroll
    for (int d = 1; d < 8; d <<= 1)
        sum += __shfl_xor_sync(~0u, sum, d, 8);
    float lse = m + logf(sum);
    if (lane < 8)
        out[(size_t)node * NC + j] = l - lse;
}

extern "C" void kernel_launch(void* const* d_in, const int* in_sizes, int n_in,
                              void* d_out, int out_size) {
    (void)out_size;
    const float* x  = nullptr; const int* ei = nullptr;
    const float* W1 = nullptr; const float* b1 = nullptr;
    const float* W2 = nullptr; const float* b2 = nullptr;
    const float* Wc = nullptr; const float* bc = nullptr;
    for (int i = 0; i < n_in; i++) {
        switch (in_sizes[i]) {
            case NN * DF:    x  = (const float*)d_in[i]; break;
            case 2 * NE:     ei = (const int*)d_in[i];   break;
            case DF * H1:    W1 = (const float*)d_in[i]; break;
            case H1 * H2:    W2 = (const float*)d_in[i]; break;
            case H2 * NC:    Wc = (const float*)d_in[i]; break;
            case H1:         b1 = (const float*)d_in[i]; break;
            case H2:         b2 = (const float*)d_in[i]; break;
            case NC:         bc = (const float*)d_in[i]; break;
            default: break;
        }
    }
    float* out = (float*)d_out;

    k_deg<<<NE / 4 / 256, 256>>>(ei);                    // 1
    k_scan_block<<<NBLK, 256>>>();                       // 2
    k_scan_top<<<1, 32>>>();                             // 3
    k_gemm1<<<(NN + GT - 1) / GT, 256>>>(x, W1);         // 4  <- profiled slot
    k_scan_add<<<NBLK, 256>>>();                         // 5
    k_place<<<NE / 4 / 256, 256>>>(ei);                  // 6
    k_gather_mid<<<NN / 8, 256>>>(b1, W2);               // 7
    k_gather2_final<<<NN / 8, 256>>>(b2, Wc, bc, out);   // 8
}

// round 17
// speedup vs baseline: 1.1765x; 1.1461x over previous
#include <cuda_runtime.h>
#include <cuda_fp16.h>
#include <cstdint>

#define NN 100000
#define NE 3200000
#define DF 128
#define H1 32
#define H2 16
#define NC 8
#define NBLK 391          // ceil(NN/256)
#define GT 128            // gemm1 node tile per block
#define WPAD 136          // sWt row length in halfs: 272 B rows -> conflict-free

// ---- scratch (device globals; zero-initialized at load; no allocs) ----
__device__ __align__(16) __half2 g_g1h[NN * (H1 / 2)]; // g1 fp16 (row = 64 B)
__device__ __align__(16) __half2 g_g2h[NN * (H2 / 2)]; // g2 fp16 (row = 32 B)
__device__ float g_dinv[NN];
__device__ int   g_cnt[NN];      // zero at entry; re-zeroed by k_scan_block
__device__ int   g_off[NN + 1];
__device__ int   g_cur[NN];
__device__ int   g_bsum[NBLK + 1];
__device__ int   g_bpref[NBLK + 1];
__device__ int   g_csr[NE];

// ---- K1: degree histogram, int4-vectorized (4 edges/thread) ----
__global__ void k_deg(const int* __restrict__ ei) {
    int i = blockIdx.x * blockDim.x + threadIdx.x;
    int4 d = __ldg((const int4*)(ei + NE) + i);
    atomicAdd(&g_cnt[d.x], 1);
    atomicAdd(&g_cnt[d.y], 1);
    atomicAdd(&g_cnt[d.z], 1);
    atomicAdd(&g_cnt[d.w], 1);
}

// ---- K2: per-block exclusive scan of cnt (+ dinv, + cnt re-zero) ----
__global__ void k_scan_block() {
    __shared__ int swarp[8];
    __shared__ int soff[8];
    int t = threadIdx.x;
    int i = blockIdx.x * 256 + t;
    int v = 0;
    if (i < NN) {
        v = g_cnt[i];
        g_cnt[i] = 0;
        g_dinv[i] = rsqrtf((float)(v + 1));
    }
    int incl = v;
#pragma unroll
    for (int d = 1; d < 32; d <<= 1) {
        int n = __shfl_up_sync(~0u, incl, d);
        if ((t & 31) >= d) incl += n;
    }
    if ((t & 31) == 31) swarp[t >> 5] = incl;
    __syncthreads();
    if (t == 0) {
        int run = 0;
#pragma unroll
        for (int w = 0; w < 8; w++) { soff[w] = run; run += swarp[w]; }
        g_bsum[blockIdx.x] = run;
    }
    __syncthreads();
    if (i < NN) g_off[i] = incl - v + soff[t >> 5];
}

// ---- K3: scan 391 block sums with ONE WARP ----
__global__ void k_scan_top() {
    const int PER = (NBLK + 31) / 32;   // 13
    int lane = threadIdx.x;
    int base = lane * PER;
    int pre[PER];
    int s = 0;
#pragma unroll
    for (int i = 0; i < PER; i++) {
        int idx = base + i;
        int v = (idx < NBLK) ? g_bsum[idx] : 0;
        pre[i] = s;
        s += v;
    }
    int incl = s;
#pragma unroll
    for (int d = 1; d < 32; d <<= 1) {
        int n = __shfl_up_sync(~0u, incl, d);
        if (lane >= d) incl += n;
    }
    int excl = incl - s;
#pragma unroll
    for (int i = 0; i < PER; i++) {
        int idx = base + i;
        if (idx < NBLK) g_bpref[idx] = excl + pre[i];
    }
}

// ---- HMMA helper ----
__device__ __forceinline__ void mma16816(float* c, uint32_t a0, uint32_t a1,
                                         uint32_t a2, uint32_t a3,
                                         uint32_t b0, uint32_t b1) {
    asm volatile(
        "mma.sync.aligned.m16n8k16.row.col.f32.f16.f16.f32 "
        "{%0,%1,%2,%3}, {%4,%5,%6,%7}, {%8,%9}, {%0,%1,%2,%3};"
        : "+f"(c[0]), "+f"(c[1]), "+f"(c[2]), "+f"(c[3])
        : "r"(a0), "r"(a1), "r"(a2), "r"(a3), "r"(b0), "r"(b1));
}

// ---- K4 (slot 4, profiled): g1 = (x @ W1) * dinv via HMMA ----
// A-fragments loaded DIRECTLY from global (x has zero reuse): per k-step each
// lane does 4 independent LDG.64 + F2FP converts. Only W1^T staged in smem.
// No per-tile barrier -> deep MLP, streaming-bound.
__global__ void k_gemm1(const float* __restrict__ x, const float* __restrict__ W1) {
    __shared__ __half sWt[H1][WPAD];    // 8.7 KB; row stride 272 B (conflict-free)
    int tid = threadIdx.x;
    for (int i = tid; i < DF * H1; i += 256) {
        int k = i >> 5, j = i & 31;
        sWt[j][k] = __float2half(W1[i]);
    }
    __syncthreads();

    int warp = tid >> 5, lane = tid & 31;
    int base = blockIdx.x * GT + warp * 16;      // this warp's 16 nodes
    int r  = lane >> 2;                          // fragment row 0..7
    int kp = (lane & 3) * 2;                     // fragment k-pair base
    int rowA = base + r, rowB = base + r + 8;
    // clamp for tail block (loads stay in-bounds; stores are guarded)
    const float* pa = x + (size_t)(rowA < NN ? rowA : NN - 1) * DF;
    const float* pb = x + (size_t)(rowB < NN ? rowB : NN - 1) * DF;
    int bn = lane >> 2, bk = (lane & 3) * 2;

    float c[4][4] = {};
#pragma unroll
    for (int kc = 0; kc < DF; kc += 16) {
        float2 f0 = *(const float2*)(pa + kc + kp);
        float2 f1 = *(const float2*)(pb + kc + kp);
        float2 f2 = *(const float2*)(pa + kc + kp + 8);
        float2 f3 = *(const float2*)(pb + kc + kp + 8);
        __half2 h0 = __floats2half2_rn(f0.x, f0.y);
        __half2 h1 = __floats2half2_rn(f1.x, f1.y);
        __half2 h2 = __floats2half2_rn(f2.x, f2.y);
        __half2 h3 = __floats2half2_rn(f3.x, f3.y);
        uint32_t a0 = *(uint32_t*)&h0, a1 = *(uint32_t*)&h1;
        uint32_t a2 = *(uint32_t*)&h2, a3 = *(uint32_t*)&h3;
#pragma unroll
        for (int t = 0; t < 4; t++) {
            uint32_t b0 = *(const uint32_t*)&sWt[t * 8 + bn][kc + bk];
            uint32_t b1 = *(const uint32_t*)&sWt[t * 8 + bn][kc + bk + 8];
            mma16816(c[t], a0, a1, a2, a3, b0, b1);
        }
    }

    // epilogue: c[t][0..1] -> row rowA cols t*8+(lane&3)*2,+1 ; c[t][2..3] -> rowB
    float dva = (rowA < NN) ? g_dinv[rowA] : 0.f;
    float dvb = (rowB < NN) ? g_dinv[rowB] : 0.f;
#pragma unroll
    for (int t = 0; t < 4; t++) {
        int hidx = t * 4 + (lane & 3);
        if (rowA < NN)
            g_g1h[(size_t)rowA * (H1 / 2) + hidx] =
                __floats2half2_rn(c[t][0] * dva, c[t][1] * dva);
        if (rowB < NN)
            g_g1h[(size_t)rowB * (H1 / 2) + hidx] =
                __floats2half2_rn(c[t][2] * dvb, c[t][3] * dvb);
    }
}

// ---- K5: add block prefixes; init cursors; off[NN]=NE ----
__global__ void k_scan_add() {
    int i = blockIdx.x * blockDim.x + threadIdx.x;
    if (i < NN) {
        int o = g_off[i] + g_bpref[i >> 8];
        g_off[i] = o;
        g_cur[i] = o;
    }
    if (i == 0) g_off[NN] = NE;
}

// ---- K6: place edges into CSR slots, int4-vectorized ----
__global__ void k_place(const int* __restrict__ ei) {
    int i = blockIdx.x * blockDim.x + threadIdx.x;
    int4 s = __ldg((const int4*)ei + i);
    int4 d = __ldg((const int4*)(ei + NE) + i);
    int p;
    p = atomicAdd(&g_cur[d.x], 1); g_csr[p] = s.x;
    p = atomicAdd(&g_cur[d.y], 1); g_csr[p] = s.y;
    p = atomicAdd(&g_cur[d.z], 1); g_csr[p] = s.z;
    p = atomicAdd(&g_cur[d.w], 1); g_csr[p] = s.w;
}

__device__ __forceinline__ void acc8(float* a, uint4 v) {
    float2 f0 = __half22float2(*(__half2*)&v.x);
    float2 f1 = __half22float2(*(__half2*)&v.y);
    float2 f2 = __half22float2(*(__half2*)&v.z);
    float2 f3 = __half22float2(*(__half2*)&v.w);
    a[0] += f0.x; a[1] += f0.y; a[2] += f1.x; a[3] += f1.y;
    a[4] += f2.x; a[5] += f2.y; a[6] += f3.x; a[7] += f3.y;
}

// ---- K7: gather layer-1 + relu + W2 matvec -> g2 fp16 ----
__global__ void k_gather_mid(const float* __restrict__ b1, const float* __restrict__ W2) {
    __shared__ float sW2[H1 * H2];
    __shared__ float su[8][H1 + 4];
    int tid = threadIdx.x;
    for (int i = tid; i < H1 * H2; i += 256) sW2[i] = W2[i];
    __syncthreads();
    int warp = tid >> 5, lane = tid & 31;
    int node = blockIdx.x * 8 + warp;
    int slot = lane >> 2, q = lane & 3;
    int s = g_off[node], t = g_off[node + 1];
    float a[8] = {0.f, 0.f, 0.f, 0.f, 0.f, 0.f, 0.f, 0.f};
    int e = s + slot;
    for (; e + 8 < t; e += 16) {
        int s0 = __ldg(&g_csr[e]);
        int s1 = __ldg(&g_csr[e + 8]);
        uint4 v0 = __ldg((const uint4*)(g_g1h + s0 * (H1 / 2)) + q);
        uint4 v1 = __ldg((const uint4*)(g_g1h + s1 * (H1 / 2)) + q);
        acc8(a, v0);
        acc8(a, v1);
    }
    if (e < t) {
        int s0 = __ldg(&g_csr[e]);
        uint4 v0 = __ldg((const uint4*)(g_g1h + s0 * (H1 / 2)) + q);
        acc8(a, v0);
    }
#pragma unroll
    for (int m = 4; m < 32; m <<= 1)
#pragma unroll
        for (int i = 0; i < 8; i++)
            a[i] += __shfl_xor_sync(~0u, a[i], m);
    uint4 sv = *((const uint4*)(g_g1h + node * (H1 / 2)) + q);
    float sl[8] = {0.f, 0.f, 0.f, 0.f, 0.f, 0.f, 0.f, 0.f};
    acc8(sl, sv);
    float dinv = g_dinv[node];
    if (slot == 0) {
        float u[8];
#pragma unroll
        for (int i = 0; i < 8; i++)
            u[i] = fmaxf(fmaf(a[i] + sl[i], dinv, __ldg(&b1[8 * q + i])), 0.f);
        ((float4*)&su[warp][8 * q])[0] = make_float4(u[0], u[1], u[2], u[3]);
        ((float4*)&su[warp][8 * q])[1] = make_float4(u[4], u[5], u[6], u[7]);
    }
    __syncwarp();
    int col = lane & 15;
    float acc = 0.f;
#pragma unroll
    for (int k = 0; k < H1; k++)
        acc = fmaf(su[warp][k], sW2[k * H2 + col], acc);
    acc *= dinv;
    float nb = __shfl_down_sync(~0u, acc, 1);
    if (lane < 16 && (lane & 1) == 0)
        g_g2h[node * (H2 / 2) + (lane >> 1)] = __floats2half2_rn(acc, nb);
}

__device__ __forceinline__ void acc4(float* a, uint2 v) {
    float2 f0 = __half22float2(*(__half2*)&v.x);
    float2 f1 = __half22float2(*(__half2*)&v.y);
    a[0] += f0.x; a[1] += f0.y; a[2] += f1.x; a[3] += f1.y;
}

// ---- K8: gather layer-2 + relu + Wc + log_softmax -> out (FUSED) ----
__global__ void k_gather2_final(const float* __restrict__ b2,
                                const float* __restrict__ Wc,
                                const float* __restrict__ bc,
                                float* __restrict__ out) {
    __shared__ float su[8][H2 + 4];   // 80 B rows, 16B-aligned
    int tid = threadIdx.x;
    int warp = tid >> 5, lane = tid & 31;
    int node = blockIdx.x * 8 + warp;
    int slot = lane >> 2, q = lane & 3;
    int s = g_off[node], t = g_off[node + 1];
    float a[4] = {0.f, 0.f, 0.f, 0.f};
    int e = s + slot;
    for (; e + 8 < t; e += 16) {
        int s0 = __ldg(&g_csr[e]);
        int s1 = __ldg(&g_csr[e + 8]);
        uint2 v0 = __ldg((const uint2*)(g_g2h + s0 * (H2 / 2)) + q);
        uint2 v1 = __ldg((const uint2*)(g_g2h + s1 * (H2 / 2)) + q);
        acc4(a, v0);
        acc4(a, v1);
    }
    if (e < t) {
        int s0 = __ldg(&g_csr[e]);
        uint2 v0 = __ldg((const uint2*)(g_g2h + s0 * (H2 / 2)) + q);
        acc4(a, v0);
    }
#pragma unroll
    for (int m = 4; m < 32; m <<= 1)
#pragma unroll
        for (int i = 0; i < 4; i++)
            a[i] += __shfl_xor_sync(~0u, a[i], m);
    float dinv = g_dinv[node];
    if (slot == 0) {
        uint2 sv = *((const uint2*)(g_g2h + node * (H2 / 2)) + q);
        acc4(a, sv);   // self loop
        float u0 = fmaxf(fmaf(a[0], dinv, __ldg(&b2[4 * q + 0])), 0.f);
        float u1 = fmaxf(fmaf(a[1], dinv, __ldg(&b2[4 * q + 1])), 0.f);
        float u2 = fmaxf(fmaf(a[2], dinv, __ldg(&b2[4 * q + 2])), 0.f);
        float u3 = fmaxf(fmaf(a[3], dinv, __ldg(&b2[4 * q + 3])), 0.f);
        *((float4*)&su[warp][4 * q]) = make_float4(u0, u1, u2, u3);
    }
    __syncwarp();
    int j = lane & 7;
    float l = __ldg(&bc[j]);
#pragma unroll
    for (int k = 0; k < H2; k++)
        l = fmaf(su[warp][k], __ldg(&Wc[k * NC + j]), l);
    float m = l;
#pragma unroll
    for (int d = 1; d < 8; d <<= 1)
        m = fmaxf(m, __shfl_xor_sync(~0u, m, d, 8));
    float ex = expf(l - m);
    float sum = ex;
#pragma unroll
    for (int d = 1; d < 8; d <<= 1)
        sum += __shfl_xor_sync(~0u, sum, d, 8);
    float lse = m + logf(sum);
    if (lane < 8)
        out[(size_t)node * NC + j] = l - lse;
}

extern "C" void kernel_launch(void* const* d_in, const int* in_sizes, int n_in,
                              void* d_out, int out_size) {
    (void)out_size;
    const float* x  = nullptr; const int* ei = nullptr;
    const float* W1 = nullptr; const float* b1 = nullptr;
    const float* W2 = nullptr; const float* b2 = nullptr;
    const float* Wc = nullptr; const float* bc = nullptr;
    for (int i = 0; i < n_in; i++) {
        switch (in_sizes[i]) {
            case NN * DF:    x  = (const float*)d_in[i]; break;
            case 2 * NE:     ei = (const int*)d_in[i];   break;
            case DF * H1:    W1 = (const float*)d_in[i]; break;
            case H1 * H2:    W2 = (const float*)d_in[i]; break;
            case H2 * NC:    Wc = (const float*)d_in[i]; break;
            case H1:         b1 = (const float*)d_in[i]; break;
            case H2:         b2 = (const float*)d_in[i]; break;
            case NC:         bc = (const float*)d_in[i]; break;
            default: break;
        }
    }
    float* out = (float*)d_out;

    k_deg<<<NE / 4 / 256, 256>>>(ei);                    // 1
    k_scan_block<<<NBLK, 256>>>();                       // 2
    k_scan_top<<<1, 32>>>();                             // 3
    k_gemm1<<<(NN + GT - 1) / GT, 256>>>(x, W1);         // 4  <- profiled slot
    k_scan_add<<<NBLK, 256>>>();                         // 5
    k_place<<<NE / 4 / 256, 256>>>(ei);                  // 6
    k_gather_mid<<<NN / 8, 256>>>(b1, W2);               // 7
    k_gather2_final<<<NN / 8, 256>>>(b2, Wc, bc, out);   // 8
}